// round 1
// baseline (speedup 1.0000x reference)
#include <cuda_runtime.h>

#define NG 128
#define NPER0 512
#define N0TOT 65536
#define E_TOT 1048576
#define EPG 8192
#define INC 100
#define HIDC 128
#define K1C 410
#define K2C 328
#define K3C 263
#define N1TOT (NG*K1C)
#define N2TOT (NG*K2C)
#define N3TOT (NG*K3C)
#define BN_EPS 1e-5f

// ---------------- device scratch (no allocations allowed) ----------------
__device__ __align__(16) float d_bufA[N0TOT*HIDC];
__device__ __align__(16) float d_bufB[N0TOT*HIDC];
__device__ float d_score[N0TOT];
__device__ float d_degf[N0TOT];
__device__ int   d_indeg[N0TOT];
__device__ int   d_coff[N0TOT];
__device__ int   d_old2new[N0TOT];
__device__ int   d_srcE[E_TOT];
__device__ int   d_dstE[E_TOT];
__device__ unsigned char d_em[E_TOT];
__device__ long long d_csr[E_TOT];
__device__ __align__(16) float d_bnsum[HIDC];
__device__ __align__(16) float d_bnsq[HIDC];
__device__ __align__(16) float d_read[3*NG*2*HIDC];
__device__ float d_attinv;

// ---------------- f32x2 packed helpers ----------------
__device__ __forceinline__ unsigned long long ffma2(unsigned long long a,
                                                    unsigned long long b,
                                                    unsigned long long c) {
    unsigned long long d;
    asm("fma.rn.f32x2 %0, %1, %2, %3;" : "=l"(d) : "l"(a), "l"(b), "l"(c));
    return d;
}
__device__ __forceinline__ unsigned long long packf2(float x, float y) {
    unsigned long long d;
    asm("mov.b64 %0, {%1, %2};" : "=l"(d) : "f"(x), "f"(y));
    return d;
}
__device__ __forceinline__ float2 unpackf2(unsigned long long d) {
    float2 r;
    asm("mov.b64 {%0, %1}, %2;" : "=f"(r.x), "=f"(r.y) : "l"(d));
    return r;
}

// ---------------- edges init ----------------
__global__ void k_edges_init(const int* __restrict__ ei) {
    int e = blockIdx.x * blockDim.x + threadIdx.x;
    if (e < E_TOT) {
        d_srcE[e] = ei[e];
        d_dstE[e] = ei[E_TOT + e];
        d_em[e] = 1;
    }
}

// ---------------- GEMM: C[M,128] = act(A[M,KT] @ W[KT,128] (+ bias)) ----------------
// 64-row tile per CTA, 256 threads, each thread 4 rows x 8 cols, f32x2 packed FMA.
template<int KT, bool BIAS_RELU>
__global__ __launch_bounds__(256) void k_gemm(const float* __restrict__ A,
                                              const float* __restrict__ W,
                                              const float* __restrict__ bias,
                                              float* __restrict__ C) {
    __shared__ float Ash[64 * 64];
    __shared__ float Wsh[64 * 128];
    const int tid = threadIdx.x;
    const int tx = tid & 15;   // 8-col group
    const int ty = tid >> 4;   // 4-row group
    const int row0 = blockIdx.x * 64;

    unsigned long long acc[4][4];
#pragma unroll
    for (int r = 0; r < 4; r++)
#pragma unroll
        for (int c = 0; c < 4; c++) acc[r][c] = 0ull;

#pragma unroll
    for (int k0 = 0; k0 < KT; k0 += 64) {
        const int kc = (KT - k0) < 64 ? (KT - k0) : 64;
        for (int i = tid; i < 64 * kc; i += 256) {
            int r = i / kc, k = i - r * kc;
            Ash[r * 64 + k] = A[(long long)(row0 + r) * KT + k0 + k];
        }
        for (int i = tid; i < kc * 128; i += 256) {
            int k = i >> 7, c = i & 127;
            Wsh[i] = W[(k0 + k) * 128 + c];
        }
        __syncthreads();
#pragma unroll 8
        for (int k = 0; k < kc; k++) {
            float a0 = Ash[(ty * 4 + 0) * 64 + k];
            float a1 = Ash[(ty * 4 + 1) * 64 + k];
            float a2 = Ash[(ty * 4 + 2) * 64 + k];
            float a3 = Ash[(ty * 4 + 3) * 64 + k];
            unsigned long long p0 = packf2(a0, a0);
            unsigned long long p1 = packf2(a1, a1);
            unsigned long long p2 = packf2(a2, a2);
            unsigned long long p3 = packf2(a3, a3);
            const ulonglong2* wp = (const ulonglong2*)&Wsh[k * 128 + tx * 8];
            ulonglong2 wA = wp[0];
            ulonglong2 wB = wp[1];
            acc[0][0] = ffma2(p0, wA.x, acc[0][0]);
            acc[0][1] = ffma2(p0, wA.y, acc[0][1]);
            acc[0][2] = ffma2(p0, wB.x, acc[0][2]);
            acc[0][3] = ffma2(p0, wB.y, acc[0][3]);
            acc[1][0] = ffma2(p1, wA.x, acc[1][0]);
            acc[1][1] = ffma2(p1, wA.y, acc[1][1]);
            acc[1][2] = ffma2(p1, wB.x, acc[1][2]);
            acc[1][3] = ffma2(p1, wB.y, acc[1][3]);
            acc[2][0] = ffma2(p2, wA.x, acc[2][0]);
            acc[2][1] = ffma2(p2, wA.y, acc[2][1]);
            acc[2][2] = ffma2(p2, wB.x, acc[2][2]);
            acc[2][3] = ffma2(p2, wB.y, acc[2][3]);
            acc[3][0] = ffma2(p3, wA.x, acc[3][0]);
            acc[3][1] = ffma2(p3, wA.y, acc[3][1]);
            acc[3][2] = ffma2(p3, wB.x, acc[3][2]);
            acc[3][3] = ffma2(p3, wB.y, acc[3][3]);
        }
        __syncthreads();
    }

    const int col0 = tx * 8;
#pragma unroll
    for (int r = 0; r < 4; r++) {
        float out[8];
#pragma unroll
        for (int c = 0; c < 4; c++) {
            float2 u = unpackf2(acc[r][c]);
            out[2 * c] = u.x;
            out[2 * c + 1] = u.y;
        }
        if (BIAS_RELU) {
#pragma unroll
            for (int i = 0; i < 8; i++) out[i] = fmaxf(out[i] + bias[col0 + i], 0.0f);
        }
        int row = row0 + ty * 4 + r;
        float4* cp = (float4*)&C[(long long)row * 128 + col0];
        cp[0] = make_float4(out[0], out[1], out[2], out[3]);
        cp[1] = make_float4(out[4], out[5], out[6], out[7]);
    }
}

// ---------------- per-graph CSR build (counts, scan, fill with coef) ----------------
__global__ __launch_bounds__(512) void k_csr(int nper) {
    __shared__ int cnt[512];
    __shared__ int cur[512];
    __shared__ int wtmp[16];
    __shared__ int wexcl[16];
    const int g = blockIdx.x;
    const int t = threadIdx.x;
    cnt[t] = 0;
    __syncthreads();
    const int e0 = g * EPG;
    for (int e = t; e < EPG; e += 512) {
        int ee = e0 + e;
        if (d_em[ee]) atomicAdd(&cnt[d_dstE[ee] - g * nper], 1);
    }
    __syncthreads();
    int v = cnt[t];
    int lane = t & 31, wid = t >> 5;
    int incl = v;
#pragma unroll
    for (int o = 1; o < 32; o <<= 1) {
        int y = __shfl_up_sync(0xffffffffu, incl, o);
        if (lane >= o) incl += y;
    }
    if (lane == 31) wtmp[wid] = incl;
    __syncthreads();
    if (t < 16) {
        int w = wtmp[t];
        int s = w;
#pragma unroll
        for (int o = 1; o < 16; o <<= 1) {
            int y = __shfl_up_sync(0x0000ffffu, s, o);
            if (t >= o) s += y;
        }
        wexcl[t] = s - w;
    }
    __syncthreads();
    int excl = incl - v + wexcl[wid];
    cur[t] = excl;
    if (t < nper) {
        int node = g * nper + t;
        d_coff[node] = e0 + excl;
        d_indeg[node] = v;
        d_degf[node] = (float)v + 1.0f;
    }
    __syncthreads();
    for (int e = t; e < EPG; e += 512) {
        int ee = e0 + e;
        if (d_em[ee]) {
            int s = d_srcE[ee];
            int dl = d_dstE[ee] - g * nper;
            int sl = s - g * nper;
            int slot = atomicAdd(&cur[dl], 1);
            float coef = rsqrtf((float)cnt[sl] + 1.0f) * rsqrtf((float)cnt[dl] + 1.0f);
            union { struct { int s; float c; } p; long long ll; } u;
            u.p.s = s;
            u.p.c = coef;
            d_csr[e0 + slot] = u.ll;
        }
    }
}

// ---------------- GCN aggregation: warp per node, register accumulation ----------------
__global__ __launch_bounds__(256) void k_conv(const float* __restrict__ xl,
                                              float* __restrict__ out,
                                              const float* __restrict__ bias, int n) {
    int gid = blockIdx.x * blockDim.x + threadIdx.x;
    int node = gid >> 5, lane = gid & 31;
    if (node >= n) return;
    const float4* x4 = (const float4*)xl;
    float4 acc = make_float4(0.f, 0.f, 0.f, 0.f);
    int base = d_coff[node];
    int cnt = d_indeg[node];
#pragma unroll 4
    for (int j = 0; j < cnt; j++) {
        long long ll = d_csr[base + j];
        int s = (int)(ll & 0xffffffffll);
        float w = __int_as_float((int)(ll >> 32));
        float4 v = x4[(long long)s * 32 + lane];
        acc.x += w * v.x;
        acc.y += w * v.y;
        acc.z += w * v.z;
        acc.w += w * v.w;
    }
    float di = 1.0f / d_degf[node];
    float4 vs = x4[(long long)node * 32 + lane];
    float4 b = ((const float4*)bias)[lane];
    acc.x += di * vs.x + b.x;
    acc.y += di * vs.y + b.y;
    acc.z += di * vs.z + b.z;
    acc.w += di * vs.w + b.w;
    ((float4*)out)[(long long)node * 32 + lane] = acc;
}

// ---------------- zero BN sums + att inv-norm ----------------
__global__ void k_bnzero_attn(const float* __restrict__ att) {
    __shared__ float sm[128];
    int t = threadIdx.x;
    d_bnsum[t] = 0.f;
    d_bnsq[t] = 0.f;
    float a = att[t];
    sm[t] = a * a;
    __syncthreads();
    for (int o = 64; o > 0; o >>= 1) {
        if (t < o) sm[t] += sm[t + o];
        __syncthreads();
    }
    if (t == 0) d_attinv = rsqrtf(sm[0]);
}

// ---------------- BN stats (sum, sumsq per channel) ----------------
__global__ __launch_bounds__(512) void k_bnstats(const float* __restrict__ x, int n) {
    int c = threadIdx.x & 127, rs = threadIdx.x >> 7;
    float s = 0.f, s2 = 0.f;
    for (int row = blockIdx.x * 4 + rs; row < n; row += gridDim.x * 4) {
        float v = x[(long long)row * 128 + c];
        s += v;
        s2 += v * v;
    }
    __shared__ float sm[512];
    __shared__ float sm2[512];
    sm[threadIdx.x] = s;
    sm2[threadIdx.x] = s2;
    __syncthreads();
    if (rs == 0) {
        s = sm[c] + sm[c + 128] + sm[c + 256] + sm[c + 384];
        s2 = sm2[c] + sm2[c + 128] + sm2[c + 256] + sm2[c + 384];
        atomicAdd(&d_bnsum[c], s);
        atomicAdd(&d_bnsq[c], s2);
    }
}

// ---------------- BN apply + relu + score (warp per node) ----------------
__global__ __launch_bounds__(256) void k_bnapply(float* __restrict__ x,
                                                 const float* __restrict__ gamma,
                                                 const float* __restrict__ beta,
                                                 const float* __restrict__ att, int n) {
    int gid = blockIdx.x * blockDim.x + threadIdx.x;
    int node = gid >> 5, lane = gid & 31;
    if (node >= n) return;
    float inv_n = 1.0f / (float)n;
    float4 su = ((const float4*)d_bnsum)[lane];
    float4 sq = ((const float4*)d_bnsq)[lane];
    float4 g4 = ((const float4*)gamma)[lane];
    float4 b4 = ((const float4*)beta)[lane];
    float4 a4 = ((const float4*)att)[lane];
    float mu, var, sc;
    float4 scale, shift;
    mu = su.x * inv_n; var = sq.x * inv_n - mu * mu; sc = g4.x * rsqrtf(var + BN_EPS);
    scale.x = sc; shift.x = b4.x - mu * sc;
    mu = su.y * inv_n; var = sq.y * inv_n - mu * mu; sc = g4.y * rsqrtf(var + BN_EPS);
    scale.y = sc; shift.y = b4.y - mu * sc;
    mu = su.z * inv_n; var = sq.z * inv_n - mu * mu; sc = g4.z * rsqrtf(var + BN_EPS);
    scale.z = sc; shift.z = b4.z - mu * sc;
    mu = su.w * inv_n; var = sq.w * inv_n - mu * mu; sc = g4.w * rsqrtf(var + BN_EPS);
    scale.w = sc; shift.w = b4.w - mu * sc;

    float4 v = ((float4*)x)[(long long)node * 32 + lane];
    float4 h;
    h.x = fmaxf(v.x * scale.x + shift.x, 0.f);
    h.y = fmaxf(v.y * scale.y + shift.y, 0.f);
    h.z = fmaxf(v.z * scale.z + shift.z, 0.f);
    h.w = fmaxf(v.w * scale.w + shift.w, 0.f);
    ((float4*)x)[(long long)node * 32 + lane] = h;

    float dot = h.x * a4.x + h.y * a4.y + h.z * a4.z + h.w * a4.w;
#pragma unroll
    for (int o = 16; o > 0; o >>= 1) dot += __shfl_xor_sync(0xffffffffu, dot, o);
    if (lane == 0) d_score[node] = tanhf(dot * d_attinv);
}

// ---------------- per-graph exact top-k (bitonic sort on packed keys) + gated gather ----------------
__global__ __launch_bounds__(512) void k_topk(const float* __restrict__ h,
                                              float* __restrict__ newh, int nper, int k) {
    __shared__ unsigned long long key[512];
    __shared__ int klocal[512];
    __shared__ float ksc[512];
    const int g = blockIdx.x, t = threadIdx.x;

    if (t < nper) d_old2new[g * nper + t] = -1;

    unsigned long long kk = 0xFFFFFFFFFFFFFFFFull;
    if (t < nper) {
        float s = d_score[g * nper + t];
        unsigned fu = __float_as_uint(s);
        unsigned asc = (fu & 0x80000000u) ? ~fu : (fu | 0x80000000u);
        unsigned dsc = ~asc;  // ascending key == descending value
        kk = ((unsigned long long)dsc << 32) | (unsigned)t;
    }
    key[t] = kk;
    __syncthreads();
    for (int sz = 2; sz <= 512; sz <<= 1) {
        for (int j = sz >> 1; j > 0; j >>= 1) {
            int ixj = t ^ j;
            if (ixj > t) {
                bool up = ((t & sz) == 0);
                unsigned long long a = key[t], b = key[ixj];
                if ((a > b) == up) {
                    key[t] = b;
                    key[ixj] = a;
                }
            }
            __syncthreads();
        }
    }
    if (t < k) {
        int local = (int)(unsigned)(key[t] & 0xffffffffull);
        d_old2new[g * nper + local] = g * k + t;
        klocal[t] = local;
        ksc[t] = d_score[g * nper + local];
    }
    __syncthreads();
    for (int idx = t; idx < k * 128; idx += 512) {
        int j = idx >> 7, c = idx & 127;
        newh[((long long)(g * k + j)) * 128 + c] =
            h[((long long)(g * nper + klocal[j])) * 128 + c] * ksc[j];
    }
}

// ---------------- readout: [max, mean] per graph ----------------
__global__ __launch_bounds__(128) void k_readout(const float* __restrict__ h, int k, int lvl) {
    int g = blockIdx.x, c = threadIdx.x;
    float mx = -3.4e38f, sm = 0.f;
    const float* base = h + (long long)g * k * 128 + c;
#pragma unroll 4
    for (int j = 0; j < k; j++) {
        float v = base[(long long)j * 128];
        mx = fmaxf(mx, v);
        sm += v;
    }
    float* out = d_read + lvl * NG * 256 + g * 256;
    out[c] = mx;
    out[128 + c] = sm / (float)k;
}

// ---------------- edge remap ----------------
__global__ void k_remap() {
    int e = blockIdx.x * blockDim.x + threadIdx.x;
    if (e >= E_TOT) return;
    if (d_em[e]) {
        int s2 = d_old2new[d_srcE[e]];
        int d2 = d_old2new[d_dstE[e]];
        if (s2 >= 0 && d2 >= 0) {
            d_srcE[e] = s2;
            d_dstE[e] = d2;
        } else {
            d_em[e] = 0;
        }
    }
}

// ---------------- final MLP ----------------
__global__ __launch_bounds__(128) void k_final(const float* __restrict__ Wl1,
                                               const float* __restrict__ bl1,
                                               const float* __restrict__ Wl2,
                                               const float* __restrict__ bl2,
                                               float* __restrict__ out) {
    __shared__ float s[256];
    __shared__ float hid[128];
    int g = blockIdx.x, t = threadIdx.x;
    for (int i = t; i < 256; i += 128)
        s[i] = d_read[0 * NG * 256 + g * 256 + i] + d_read[1 * NG * 256 + g * 256 + i] +
               d_read[2 * NG * 256 + g * 256 + i];
    __syncthreads();
    float acc = bl1[t];
#pragma unroll 8
    for (int j = 0; j < 256; j++) acc += s[j] * Wl1[j * 128 + t];
    hid[t] = fmaxf(acc, 0.f);
    __syncthreads();
    if (t < 64) {
        int o = t >> 5, lane = t & 31;
        float p = 0.f;
#pragma unroll
        for (int j = lane; j < 128; j += 32) p += hid[j] * Wl2[j * 2 + o];
#pragma unroll
        for (int off = 16; off > 0; off >>= 1) p += __shfl_xor_sync(0xffffffffu, p, off);
        if (lane == 0) out[g * 2 + o] = p + bl2[o];
    }
}

// ---------------- orchestration ----------------
extern "C" void kernel_launch(void* const* d_in, const int* in_sizes, int n_in,
                              void* d_out, int out_size) {
    (void)in_sizes; (void)n_in; (void)out_size;
    const float* x = (const float*)d_in[0];
    const int* ei = (const int*)d_in[1];
    const float* Wp = (const float*)d_in[3];
    const float* bp = (const float*)d_in[4];
    const float* Wc[3] = {(const float*)d_in[5], (const float*)d_in[10], (const float*)d_in[15]};
    const float* bc[3] = {(const float*)d_in[6], (const float*)d_in[11], (const float*)d_in[16]};
    const float* gc[3] = {(const float*)d_in[7], (const float*)d_in[12], (const float*)d_in[17]};
    const float* be[3] = {(const float*)d_in[8], (const float*)d_in[13], (const float*)d_in[18]};
    const float* at[3] = {(const float*)d_in[9], (const float*)d_in[14], (const float*)d_in[19]};
    const float* Wl1 = (const float*)d_in[20];
    const float* bl1 = (const float*)d_in[21];
    const float* Wl2 = (const float*)d_in[22];
    const float* bl2 = (const float*)d_in[23];

    float *bufA, *bufB;
    cudaGetSymbolAddress((void**)&bufA, d_bufA);
    cudaGetSymbolAddress((void**)&bufB, d_bufB);

    k_edges_init<<<E_TOT / 256, 256>>>(ei);
    k_gemm<INC, true><<<N0TOT / 64, 256>>>(x, Wp, bp, bufA);

    const int ns[3] = {N0TOT, N1TOT, N2TOT};
    const int npers[3] = {NPER0, K1C, K2C};
    const int ks[3] = {K1C, K2C, K3C};
    float* hin = bufA;
    float* halt = bufB;
    for (int l = 0; l < 3; l++) {
        const int n = ns[l], nper = npers[l], k = ks[l];
        k_gemm<HIDC, false><<<n / 64, 256>>>(hin, Wc[l], nullptr, halt);  // xl -> halt
        k_csr<<<NG, 512>>>(nper);
        k_conv<<<(n * 32 + 255) / 256, 256>>>(halt, hin, bc[l], n);       // conv -> hin
        k_bnzero_attn<<<1, 128>>>(at[l]);
        k_bnstats<<<1024, 512>>>(hin, n);
        k_bnapply<<<(n * 32 + 255) / 256, 256>>>(hin, gc[l], be[l], at[l], n);
        k_topk<<<NG, 512>>>(hin, halt, nper, k);                          // gated newh -> halt
        k_readout<<<NG, 128>>>(halt, k, l);
        if (l < 2) k_remap<<<E_TOT / 256, 256>>>();
        float* tmp = hin;
        hin = halt;
        halt = tmp;
    }
    k_final<<<NG, 128>>>(Wl1, bl1, Wl2, bl2, (float*)d_out);
}

// round 5
// speedup vs baseline: 1.0389x; 1.0389x over previous
#include <cuda_runtime.h>

#define NG 128
#define NPER0 512
#define N0TOT 65536
#define E_TOT 1048576
#define EPG 8192
#define INC 100
#define HIDC 128
#define K1C 410
#define K2C 328
#define K3C 263
#define N1TOT (NG*K1C)
#define N2TOT (NG*K2C)
#define N3TOT (NG*K3C)
#define BN_EPS 1e-5f

// ---------------- device scratch ----------------
__device__ __align__(16) float d_bufA[N0TOT*HIDC];
__device__ __align__(16) float d_bufB[N0TOT*HIDC];
__device__ int   d_indeg[NG*NPER0];
__device__ int   d_coff[NG*NPER0];
__device__ int   d_cur[NG*NPER0];
__device__ float d_dinv[NG*NPER0];
__device__ int   d_old2new[NG*NPER0];
__device__ int   d_srcE[E_TOT];
__device__ int   d_dstE[E_TOT];
__device__ unsigned char d_em[E_TOT];
__device__ long long d_csr[E_TOT];
__device__ __align__(16) float d_bnsum[HIDC];
__device__ __align__(16) float d_bnsq[HIDC];
__device__ __align__(16) float d_read[3*NG*2*HIDC];
__device__ float d_attinv;

// ---------------- f32x2 packed helpers ----------------
__device__ __forceinline__ unsigned long long ffma2(unsigned long long a,
                                                    unsigned long long b,
                                                    unsigned long long c) {
    unsigned long long d;
    asm("fma.rn.f32x2 %0, %1, %2, %3;" : "=l"(d) : "l"(a), "l"(b), "l"(c));
    return d;
}
__device__ __forceinline__ unsigned long long packf2(float x, float y) {
    unsigned long long d;
    asm("mov.b64 %0, {%1, %2};" : "=l"(d) : "f"(x), "f"(y));
    return d;
}
__device__ __forceinline__ float2 unpackf2(unsigned long long d) {
    float2 r;
    asm("mov.b64 {%0, %1}, %2;" : "=f"(r.x), "=f"(r.y) : "l"(d));
    return r;
}

// ---------------- GEMM: C[M,128] = act(A[M,KT] @ W[KT,128] (+ bias)) ----------------
template<int KT, bool BIAS_RELU>
__global__ __launch_bounds__(256) void k_gemm(const float* __restrict__ A,
                                              const float* __restrict__ W,
                                              const float* __restrict__ bias,
                                              float* __restrict__ C) {
    __shared__ float Ash[64 * 64];
    __shared__ float Wsh[64 * 128];
    const int tid = threadIdx.x;
    const int tx = tid & 15;
    const int ty = tid >> 4;
    const int row0 = blockIdx.x * 64;

    unsigned long long acc[4][4];
#pragma unroll
    for (int r = 0; r < 4; r++)
#pragma unroll
        for (int c = 0; c < 4; c++) acc[r][c] = 0ull;

#pragma unroll
    for (int k0 = 0; k0 < KT; k0 += 64) {
        const int kc = (KT - k0) < 64 ? (KT - k0) : 64;
        for (int i = tid; i < 64 * kc; i += 256) {
            int r = i / kc, k = i - r * kc;
            Ash[r * 64 + k] = A[(long long)(row0 + r) * KT + k0 + k];
        }
        for (int i = tid; i < kc * 128; i += 256) {
            int k = i >> 7, c = i & 127;
            Wsh[i] = W[(k0 + k) * 128 + c];
        }
        __syncthreads();
#pragma unroll 8
        for (int k = 0; k < kc; k++) {
            float a0 = Ash[(ty * 4 + 0) * 64 + k];
            float a1 = Ash[(ty * 4 + 1) * 64 + k];
            float a2 = Ash[(ty * 4 + 2) * 64 + k];
            float a3 = Ash[(ty * 4 + 3) * 64 + k];
            unsigned long long p0 = packf2(a0, a0);
            unsigned long long p1 = packf2(a1, a1);
            unsigned long long p2 = packf2(a2, a2);
            unsigned long long p3 = packf2(a3, a3);
            const ulonglong2* wp = (const ulonglong2*)&Wsh[k * 128 + tx * 8];
            ulonglong2 wA = wp[0];
            ulonglong2 wB = wp[1];
            acc[0][0] = ffma2(p0, wA.x, acc[0][0]);
            acc[0][1] = ffma2(p0, wA.y, acc[0][1]);
            acc[0][2] = ffma2(p0, wB.x, acc[0][2]);
            acc[0][3] = ffma2(p0, wB.y, acc[0][3]);
            acc[1][0] = ffma2(p1, wA.x, acc[1][0]);
            acc[1][1] = ffma2(p1, wA.y, acc[1][1]);
            acc[1][2] = ffma2(p1, wB.x, acc[1][2]);
            acc[1][3] = ffma2(p1, wB.y, acc[1][3]);
            acc[2][0] = ffma2(p2, wA.x, acc[2][0]);
            acc[2][1] = ffma2(p2, wA.y, acc[2][1]);
            acc[2][2] = ffma2(p2, wB.x, acc[2][2]);
            acc[2][3] = ffma2(p2, wB.y, acc[2][3]);
            acc[3][0] = ffma2(p3, wA.x, acc[3][0]);
            acc[3][1] = ffma2(p3, wA.y, acc[3][1]);
            acc[3][2] = ffma2(p3, wB.x, acc[3][2]);
            acc[3][3] = ffma2(p3, wB.y, acc[3][3]);
        }
        __syncthreads();
    }

    const int col0 = tx * 8;
#pragma unroll
    for (int r = 0; r < 4; r++) {
        float out[8];
#pragma unroll
        for (int c = 0; c < 4; c++) {
            float2 u = unpackf2(acc[r][c]);
            out[2 * c] = u.x;
            out[2 * c + 1] = u.y;
        }
        if (BIAS_RELU) {
#pragma unroll
            for (int i = 0; i < 8; i++) out[i] = fmaxf(out[i] + bias[col0 + i], 0.0f);
        }
        int row = row0 + ty * 4 + r;
        float4* cp = (float4*)&C[(long long)row * 128 + col0];
        cp[0] = make_float4(out[0], out[1], out[2], out[3]);
        cp[1] = make_float4(out[4], out[5], out[6], out[7]);
    }
}

// ---------------- level-0 degree count (edge-parallel, local ids) ----------------
__global__ void k_count0(const int* __restrict__ ei) {
    int e = blockIdx.x * blockDim.x + threadIdx.x;
    if (e >= E_TOT) return;
    // edges of graph g live in [g*EPG, (g+1)*EPG); node ids in [g*512, (g+1)*512)
    atomicAdd(&d_indeg[ei[E_TOT + e]], 1);   // global id == g*512+local for level 0
}

// ---------------- per-graph exclusive scan of in-degrees; also zero BN + attinv ----------------
__global__ __launch_bounds__(512) void k_scan(const float* __restrict__ att, int nper) {
    __shared__ int wtmp[16];
    __shared__ int wexcl[16];
    const int g = blockIdx.x, t = threadIdx.x;
    const int lane = t & 31, wid = t >> 5;
    if (g == 0) {
        if (t < 128) { d_bnsum[t] = 0.f; d_bnsq[t] = 0.f; }
        if (t >= 128 && t < 160) {
            int l = t - 128;
            float a0 = att[l], a1 = att[l + 32], a2 = att[l + 64], a3 = att[l + 96];
            float s = a0 * a0 + a1 * a1 + a2 * a2 + a3 * a3;
#pragma unroll
            for (int o = 16; o > 0; o >>= 1) s += __shfl_xor_sync(0xffffffffu, s, o);
            if (l == 0) d_attinv = rsqrtf(s);
        }
    }
    int v = (t < nper) ? d_indeg[g * 512 + t] : 0;
    int incl = v;
#pragma unroll
    for (int o = 1; o < 32; o <<= 1) {
        int y = __shfl_up_sync(0xffffffffu, incl, o);
        if (lane >= o) incl += y;
    }
    if (lane == 31) wtmp[wid] = incl;
    __syncthreads();
    if (t < 16) {
        int w = wtmp[t];
        int s = w;
#pragma unroll
        for (int o = 1; o < 16; o <<= 1) {
            int y = __shfl_up_sync(0x0000ffffu, s, o);
            if (t >= o) s += y;
        }
        wexcl[t] = s - w;
    }
    __syncthreads();
    int excl = incl - v + wexcl[wid];
    if (t < nper) {
        int node = g * 512 + t;
        d_coff[node] = g * EPG + excl;
        d_cur[node] = g * EPG + excl;
        d_dinv[node] = rsqrtf((float)v + 1.0f);
    }
}

// ---------------- CSR fill (edge-parallel), level-0 from ei / generic from d_srcE ----------------
__global__ void k_fill0(const int* __restrict__ ei) {
    int e = blockIdx.x * blockDim.x + threadIdx.x;
    if (e >= E_TOT) return;
    int g = e >> 13;
    int sg = ei[e];                 // global == g*512+local
    int dg = ei[E_TOT + e];
    int slot = atomicAdd(&d_cur[dg], 1);
    float coef = d_dinv[sg] * d_dinv[dg];
    union { struct { int s; float c; } p; long long ll; } u;
    u.p.s = sg - (g << 9);          // store LOCAL src id
    u.p.c = coef;
    d_csr[slot] = u.ll;
}

__global__ void k_fill(void) {
    int e = blockIdx.x * blockDim.x + threadIdx.x;
    if (e >= E_TOT) return;
    if (!d_em[e]) return;
    int g = e >> 13;
    int sl = d_srcE[e], dl = d_dstE[e];           // local ids
    int slot = atomicAdd(&d_cur[(g << 9) + dl], 1);
    float coef = d_dinv[(g << 9) + sl] * d_dinv[(g << 9) + dl];
    union { struct { int s; float c; } p; long long ll; } u;
    u.p.s = sl;
    u.p.c = coef;
    d_csr[slot] = u.ll;
}

// ---------------- conv: smem-tiled gather + fused BN stats ----------------
// grid = (NG, 2); channel-half per blockIdx.y; dynamic smem nper*64 floats
__global__ __launch_bounds__(512) void k_conv(const float* __restrict__ xl,
                                              float* __restrict__ out,
                                              const float* __restrict__ bias,
                                              int nper) {
    extern __shared__ float sf[];
    const int g = blockIdx.x, half = blockIdx.y;
    const int t = threadIdx.x, wid = t >> 5, lane = t & 31;
    const long long rb = (long long)g * nper;

    for (int idx = t; idx < nper * 16; idx += 512) {
        int r = idx >> 4, q = idx & 15;
        ((float4*)sf)[r * 16 + q] =
            ((const float4*)(xl + (rb + r) * 128 + half * 64))[q];
    }
    __syncthreads();

    const int c0 = half * 64 + lane * 2;
    const float b0 = bias[c0], b1 = bias[c0 + 1];
    float bs0 = 0.f, bs1 = 0.f, bq0 = 0.f, bq1 = 0.f;

    for (int node = wid; node < nper; node += 16) {
        int base = d_coff[(g << 9) + node];
        int cnt = d_indeg[(g << 9) + node];
        float a0 = 0.f, a1 = 0.f;
#pragma unroll 4
        for (int j = 0; j < cnt; j++) {
            long long ll = d_csr[base + j];
            int sl = (int)(ll & 0xffffffffll);
            float w = __int_as_float((int)(ll >> 32));
            float2 v = *(const float2*)&sf[sl * 64 + lane * 2];
            a0 += w * v.x;
            a1 += w * v.y;
        }
        float di = d_dinv[(g << 9) + node];
        float di2 = di * di;
        float2 s = *(const float2*)&sf[node * 64 + lane * 2];
        a0 += di2 * s.x + b0;
        a1 += di2 * s.y + b1;
        *(float2*)(out + (rb + node) * 128 + c0) = make_float2(a0, a1);
        bs0 += a0; bs1 += a1;
        bq0 += a0 * a0; bq1 += a1 * a1;
    }
    __syncthreads();
    int ch = lane * 2;
    sf[wid * 64 + ch] = bs0;
    sf[wid * 64 + ch + 1] = bs1;
    sf[1024 + wid * 64 + ch] = bq0;
    sf[1024 + wid * 64 + ch + 1] = bq1;
    __syncthreads();
    if (t < 64) {
        float s = 0.f, q = 0.f;
#pragma unroll
        for (int w = 0; w < 16; w++) {
            s += sf[w * 64 + t];
            q += sf[1024 + w * 64 + t];
        }
        atomicAdd(&d_bnsum[half * 64 + t], s);
        atomicAdd(&d_bnsq[half * 64 + t], q);
    }
}

// ---------------- fused: BN-apply + score + exact top-k + gated gather + readout ----------------
__global__ __launch_bounds__(512) void k_topk(const float* __restrict__ X,
                                              float* __restrict__ newh,
                                              const float* __restrict__ gamma,
                                              const float* __restrict__ beta,
                                              const float* __restrict__ att,
                                              int nper, int k, int ntot, int lvl) {
    __shared__ float sscale[128];
    __shared__ float sshift[128];
    __shared__ float satt[128];
    __shared__ float score[512];
    __shared__ unsigned long long key[512];
    __shared__ int klocal[512];
    __shared__ float ksc[512];
    __shared__ float red[1024];
    const int g = blockIdx.x, t = threadIdx.x, wid = t >> 5, lane = t & 31;

    if (t < 128) {
        float inv_n = 1.0f / (float)ntot;
        float mu = d_bnsum[t] * inv_n;
        float var = d_bnsq[t] * inv_n - mu * mu;
        float sc = gamma[t] * rsqrtf(var + BN_EPS);
        sscale[t] = sc;
        sshift[t] = beta[t] - mu * sc;
        satt[t] = att[t];
    }
    if (t < nper) d_old2new[(g << 9) + t] = -1;
    d_indeg[(g << 9) + t] = 0;   // zero counts for next level's remap
    __syncthreads();

    const long long rb = (long long)g * nper;
    const float ainv = d_attinv;
    for (int node = wid; node < nper; node += 16) {
        float4 v = ((const float4*)(X + (rb + node) * 128))[lane];
        int c = lane * 4;
        float h0 = fmaxf(v.x * sscale[c] + sshift[c], 0.f);
        float h1 = fmaxf(v.y * sscale[c + 1] + sshift[c + 1], 0.f);
        float h2 = fmaxf(v.z * sscale[c + 2] + sshift[c + 2], 0.f);
        float h3 = fmaxf(v.w * sscale[c + 3] + sshift[c + 3], 0.f);
        float dot = h0 * satt[c] + h1 * satt[c + 1] + h2 * satt[c + 2] + h3 * satt[c + 3];
#pragma unroll
        for (int o = 16; o > 0; o >>= 1) dot += __shfl_xor_sync(0xffffffffu, dot, o);
        if (lane == 0) score[node] = tanhf(dot * ainv);
    }
    __syncthreads();

    unsigned long long kk = 0xFFFFFFFFFFFFFFFFull;
    if (t < nper) {
        unsigned fu = __float_as_uint(score[t]);
        unsigned asc = (fu & 0x80000000u) ? ~fu : (fu | 0x80000000u);
        kk = ((unsigned long long)(~asc) << 32) | (unsigned)t;  // (desc value, asc index)
    }
    key[t] = kk;
    __syncthreads();
    for (int sz = 2; sz <= 512; sz <<= 1) {
        for (int j = sz >> 1; j > 0; j >>= 1) {
            int ixj = t ^ j;
            if (ixj > t) {
                bool up = ((t & sz) == 0);
                unsigned long long a = key[t], b = key[ixj];
                if ((a > b) == up) {
                    key[t] = b;
                    key[ixj] = a;
                }
            }
            __syncthreads();
        }
    }
    if (t < k) {
        int local = (int)(unsigned)(key[t] & 0xffffffffull);
        d_old2new[(g << 9) + local] = t;   // new LOCAL id
        klocal[t] = local;
        ksc[t] = score[local];
    }
    __syncthreads();

    // gather + BN-relu recompute + gate + readout partials (c fixed per thread)
    const int c = t & 127;
    const float sc = sscale[c], sh = sshift[c];
    float mx = -3.4e38f, sm = 0.f;
    for (int j = t >> 7; j < k; j += 4) {
        float raw = X[(rb + klocal[j]) * 128 + c];
        float val = fmaxf(raw * sc + sh, 0.f) * ksc[j];
        newh[((long long)(g * k + j)) * 128 + c] = val;
        mx = fmaxf(mx, val);
        sm += val;
    }
    red[t] = mx;
    red[512 + t] = sm;
    __syncthreads();
    if (t < 128) {
        float m = fmaxf(fmaxf(red[t], red[t + 128]), fmaxf(red[t + 256], red[t + 384]));
        float s = red[512 + t] + red[512 + t + 128] + red[512 + t + 256] + red[512 + t + 384];
        float* o = d_read + lvl * NG * 256 + g * 256;
        o[t] = m;
        o[128 + t] = s / (float)k;
    }
}

// ---------------- edge remap (+ next-level degree count), level-0 and generic ----------------
__global__ void k_remap0(const int* __restrict__ ei) {
    int e = blockIdx.x * blockDim.x + threadIdx.x;
    if (e >= E_TOT) return;
    int g = e >> 13;
    int s2 = d_old2new[ei[e]];           // global id == old2new index at level 0
    int d2 = d_old2new[ei[E_TOT + e]];
    if (s2 >= 0 && d2 >= 0) {
        d_srcE[e] = s2;
        d_dstE[e] = d2;
        d_em[e] = 1;
        atomicAdd(&d_indeg[(g << 9) + d2], 1);
    } else {
        d_em[e] = 0;
    }
}

__global__ void k_remap(void) {
    int e = blockIdx.x * blockDim.x + threadIdx.x;
    if (e >= E_TOT) return;
    if (!d_em[e]) return;
    int g = e >> 13;
    int s2 = d_old2new[(g << 9) + d_srcE[e]];
    int d2 = d_old2new[(g << 9) + d_dstE[e]];
    if (s2 >= 0 && d2 >= 0) {
        d_srcE[e] = s2;
        d_dstE[e] = d2;
        atomicAdd(&d_indeg[(g << 9) + d2], 1);
    } else {
        d_em[e] = 0;
    }
}

// ---------------- final MLP ----------------
__global__ __launch_bounds__(128) void k_final(const float* __restrict__ Wl1,
                                               const float* __restrict__ bl1,
                                               const float* __restrict__ Wl2,
                                               const float* __restrict__ bl2,
                                               float* __restrict__ out) {
    __shared__ float s[256];
    __shared__ float hid[128];
    int g = blockIdx.x, t = threadIdx.x;
    for (int i = t; i < 256; i += 128)
        s[i] = d_read[0 * NG * 256 + g * 256 + i] + d_read[1 * NG * 256 + g * 256 + i] +
               d_read[2 * NG * 256 + g * 256 + i];
    __syncthreads();
    float acc = bl1[t];
#pragma unroll 8
    for (int j = 0; j < 256; j++) acc += s[j] * Wl1[j * 128 + t];
    hid[t] = fmaxf(acc, 0.f);
    __syncthreads();
    if (t < 64) {
        int o = t >> 5, lane = t & 31;
        float p = 0.f;
#pragma unroll
        for (int j = lane; j < 128; j += 32) p += hid[j] * Wl2[j * 2 + o];
#pragma unroll
        for (int off = 16; off > 0; off >>= 1) p += __shfl_xor_sync(0xffffffffu, p, off);
        if (lane == 0) out[g * 2 + o] = p + bl2[o];
    }
}

// ---------------- orchestration ----------------
extern "C" void kernel_launch(void* const* d_in, const int* in_sizes, int n_in,
                              void* d_out, int out_size) {
    (void)in_sizes; (void)n_in; (void)out_size;
    const float* x = (const float*)d_in[0];
    const int* ei = (const int*)d_in[1];
    const float* Wp = (const float*)d_in[3];
    const float* bp = (const float*)d_in[4];
    const float* Wc[3] = {(const float*)d_in[5], (const float*)d_in[10], (const float*)d_in[15]};
    const float* bc[3] = {(const float*)d_in[6], (const float*)d_in[11], (const float*)d_in[16]};
    const float* gc[3] = {(const float*)d_in[7], (const float*)d_in[12], (const float*)d_in[17]};
    const float* be[3] = {(const float*)d_in[8], (const float*)d_in[13], (const float*)d_in[18]};
    const float* at[3] = {(const float*)d_in[9], (const float*)d_in[14], (const float*)d_in[19]};
    const float* Wl1 = (const float*)d_in[20];
    const float* bl1 = (const float*)d_in[21];
    const float* Wl2 = (const float*)d_in[22];
    const float* bl2 = (const float*)d_in[23];

    float *bufA, *bufB;
    int* indegP;
    cudaGetSymbolAddress((void**)&bufA, d_bufA);
    cudaGetSymbolAddress((void**)&bufB, d_bufB);
    cudaGetSymbolAddress((void**)&indegP, d_indeg);

    static int smem_set = 0;
    if (!smem_set) {
        cudaFuncSetAttribute(k_conv, cudaFuncAttributeMaxDynamicSharedMemorySize,
                             NPER0 * 64 * (int)sizeof(float));
        smem_set = 1;
    }

    cudaMemsetAsync(indegP, 0, NG * NPER0 * sizeof(int));
    k_count0<<<E_TOT / 256, 256>>>(ei);
    k_gemm<INC, true><<<N0TOT / 64, 256>>>(x, Wp, bp, bufA);

    // ---- level 0 ----
    k_scan<<<NG, 512>>>(at[0], NPER0);
    k_fill0<<<E_TOT / 256, 256>>>(ei);
    k_gemm<HIDC, false><<<N0TOT / 64, 256>>>(bufA, Wc[0], nullptr, bufB);
    k_conv<<<dim3(NG, 2), 512, NPER0 * 64 * sizeof(float)>>>(bufB, bufA, bc[0], NPER0);
    k_topk<<<NG, 512>>>(bufA, bufB, gc[0], be[0], at[0], NPER0, K1C, N0TOT, 0);
    k_remap0<<<E_TOT / 256, 256>>>(ei);

    // ---- level 1 ----
    k_scan<<<NG, 512>>>(at[1], K1C);
    k_fill<<<E_TOT / 256, 256>>>();
    k_gemm<HIDC, false><<<N1TOT / 64, 256>>>(bufB, Wc[1], nullptr, bufA);
    k_conv<<<dim3(NG, 2), 512, K1C * 64 * sizeof(float)>>>(bufA, bufB, bc[1], K1C);
    k_topk<<<NG, 512>>>(bufB, bufA, gc[1], be[1], at[1], K1C, K2C, N1TOT, 1);
    k_remap<<<E_TOT / 256, 256>>>();

    // ---- level 2 ----
    k_scan<<<NG, 512>>>(at[2], K2C);
    k_fill<<<E_TOT / 256, 256>>>();
    k_gemm<HIDC, false><<<N2TOT / 64, 256>>>(bufA, Wc[2], nullptr, bufB);
    k_conv<<<dim3(NG, 2), 512, K2C * 64 * sizeof(float)>>>(bufB, bufA, bc[2], K2C);
    k_topk<<<NG, 512>>>(bufA, bufB, gc[2], be[2], at[2], K2C, K3C, N2TOT, 2);

    k_final<<<NG, 128>>>(Wl1, bl1, Wl2, bl2, (float*)d_out);
}

// round 11
// speedup vs baseline: 1.1075x; 1.0660x over previous
#include <cuda_runtime.h>

#define NG 128
#define NPER0 512
#define N0TOT 65536
#define E_TOT 1048576
#define EPG 8192
#define INC 100
#define HIDC 128
#define K1C 410
#define K2C 328
#define K3C 263
#define N1TOT (NG*K1C)
#define N2TOT (NG*K2C)
#define BN_EPS 1e-5f

// ---------------- device scratch ----------------
__device__ __align__(16) float d_bufA[N0TOT*HIDC];
__device__ __align__(16) float d_bufB[N0TOT*HIDC];
__device__ int   d_indeg[NG*NPER0];
__device__ int   d_coff[NG*NPER0];
__device__ float d_dinv[NG*NPER0];
__device__ int   d_srcE[E_TOT];
__device__ int   d_dstE[E_TOT];
__device__ unsigned char d_em[E_TOT];
__device__ long long d_csr[E_TOT];
__device__ __align__(16) float d_bnsum3[3][HIDC];
__device__ __align__(16) float d_bnsq3[3][HIDC];
__device__ float d_attinv3[3];
__device__ __align__(16) float d_read[3*NG*2*HIDC];

// ---------------- f32x2 packed helpers ----------------
__device__ __forceinline__ unsigned long long ffma2(unsigned long long a,
                                                    unsigned long long b,
                                                    unsigned long long c) {
    unsigned long long d;
    asm("fma.rn.f32x2 %0, %1, %2, %3;" : "=l"(d) : "l"(a), "l"(b), "l"(c));
    return d;
}
__device__ __forceinline__ unsigned long long packf2(float x, float y) {
    unsigned long long d;
    asm("mov.b64 %0, {%1, %2};" : "=l"(d) : "f"(x), "f"(y));
    return d;
}
__device__ __forceinline__ float2 unpackf2(unsigned long long d) {
    float2 r;
    asm("mov.b64 {%0, %1}, %2;" : "=f"(r.x), "=f"(r.y) : "l"(d));
    return r;
}

// ================= init: edge load + count + scan + CSR fill (level 0) ===========
__global__ __launch_bounds__(512) void k_init(const int* __restrict__ ei,
                                              const float* __restrict__ at0,
                                              const float* __restrict__ at1,
                                              const float* __restrict__ at2) {
    __shared__ int scnt[512];
    __shared__ int rk[EPG];
    __shared__ float dv[512];
    __shared__ int wtmp[16], wexcl[16];
    const int g = blockIdx.x, t = threadIdx.x, lane = t & 31, wid = t >> 5;
    scnt[t] = 0;
    if (g == 0) {
        if (t < 384) {
            ((float*)d_bnsum3)[t] = 0.f;
            ((float*)d_bnsq3)[t] = 0.f;
        }
        if (wid >= 13) {
            const float* ap = (wid == 13) ? at0 : (wid == 14) ? at1 : at2;
            float s = 0.f;
#pragma unroll
            for (int q = 0; q < 4; q++) { float v = ap[lane + 32 * q]; s += v * v; }
#pragma unroll
            for (int o = 16; o > 0; o >>= 1) s += __shfl_xor_sync(0xffffffffu, s, o);
            if (lane == 0) d_attinv3[wid - 13] = rsqrtf(s);
        }
    }
    __syncthreads();
    const int e0 = g * EPG;
    for (int i = t; i < EPG; i += 512) {
        int sl = ei[e0 + i] - (g << 9);
        int dl = ei[E_TOT + e0 + i] - (g << 9);
        rk[i] = atomicAdd(&scnt[dl], 1);
        d_srcE[e0 + i] = sl;
        d_dstE[e0 + i] = dl;
        d_em[e0 + i] = 1;
    }
    __syncthreads();
    // per-graph exclusive scan of counts
    int v = scnt[t];
    int incl = v;
#pragma unroll
    for (int o = 1; o < 32; o <<= 1) {
        int y = __shfl_up_sync(0xffffffffu, incl, o);
        if (lane >= o) incl += y;
    }
    if (lane == 31) wtmp[wid] = incl;
    __syncthreads();
    if (t < 16) {
        int w = wtmp[t], s = w;
#pragma unroll
        for (int o = 1; o < 16; o <<= 1) {
            int y = __shfl_up_sync(0x0000ffffu, s, o);
            if (t >= o) s += y;
        }
        wexcl[t] = s - w;
    }
    __syncthreads();
    int excl = incl - v + wexcl[wid];
    {
        int node = (g << 9) + t;
        d_coff[node] = e0 + excl;
        d_indeg[node] = v;
        float di = rsqrtf((float)v + 1.f);
        d_dinv[node] = di;
        dv[t] = di;
        scnt[t] = excl;   // reuse as local offsets
    }
    __syncthreads();
    for (int i = t; i < EPG; i += 512) {
        int sl = d_srcE[e0 + i], dl = d_dstE[e0 + i];
        int slot = scnt[dl] + rk[i];
        union { struct { int s; float c; } p; long long ll; } u;
        u.p.s = sl;
        u.p.c = dv[sl] * dv[dl];
        d_csr[e0 + slot] = u.ll;
    }
}

// ================= fused GEMM: h=relu(x@Wp+bp); xl = h@W1 ===============
__global__ __launch_bounds__(256) void k_gemm2(const float* __restrict__ X,
                                               const float* __restrict__ Wp,
                                               const float* __restrict__ bp,
                                               const float* __restrict__ W1,
                                               float* __restrict__ C) {
    extern __shared__ float smp[];
    float* Ash = smp;                 // 64*64
    float* Wsh = smp + 64 * 64;       // 64*128
    float* Hs  = smp + 64 * 64 + 64 * 128;  // 64*128
    const int tid = threadIdx.x;
    const int tx = tid & 15, ty = tid >> 4;
    const int row0 = blockIdx.x * 64;

    unsigned long long acc[4][4];
#pragma unroll
    for (int r = 0; r < 4; r++)
#pragma unroll
        for (int c = 0; c < 4; c++) acc[r][c] = 0ull;

    // ---- phase A: x @ Wp (K=100) ----
#pragma unroll
    for (int k0 = 0; k0 < INC; k0 += 64) {
        const int kc = (INC - k0) < 64 ? (INC - k0) : 64;
        for (int i = tid; i < 64 * kc; i += 256) {
            int r = i / kc, k = i - r * kc;
            Ash[r * 64 + k] = X[(long long)(row0 + r) * INC + k0 + k];
        }
        for (int i = tid; i < kc * 128; i += 256) {
            int k = i >> 7, c = i & 127;
            Wsh[i] = Wp[(k0 + k) * 128 + c];
        }
        __syncthreads();
#pragma unroll 4
        for (int k = 0; k < kc; k++) {
            unsigned long long p[4];
#pragma unroll
            for (int r = 0; r < 4; r++) {
                float a = Ash[(ty * 4 + r) * 64 + k];
                p[r] = packf2(a, a);
            }
            const ulonglong2* wp = (const ulonglong2*)&Wsh[k * 128 + tx * 8];
            ulonglong2 wA = wp[0], wB = wp[1];
#pragma unroll
            for (int r = 0; r < 4; r++) {
                acc[r][0] = ffma2(p[r], wA.x, acc[r][0]);
                acc[r][1] = ffma2(p[r], wA.y, acc[r][1]);
                acc[r][2] = ffma2(p[r], wB.x, acc[r][2]);
                acc[r][3] = ffma2(p[r], wB.y, acc[r][3]);
            }
        }
        __syncthreads();
    }
    // bias + relu -> Hs
    const int col0 = tx * 8;
#pragma unroll
    for (int r = 0; r < 4; r++) {
#pragma unroll
        for (int c = 0; c < 4; c++) {
            float2 u = unpackf2(acc[r][c]);
            Hs[(ty * 4 + r) * 128 + col0 + 2 * c]     = fmaxf(u.x + bp[col0 + 2 * c], 0.f);
            Hs[(ty * 4 + r) * 128 + col0 + 2 * c + 1] = fmaxf(u.y + bp[col0 + 2 * c + 1], 0.f);
            acc[r][c] = 0ull;
        }
    }
    __syncthreads();

    // ---- phase B: Hs @ W1 (K=128) ----
#pragma unroll
    for (int k0 = 0; k0 < 128; k0 += 64) {
        for (int i = tid; i < 64 * 128; i += 256) {
            int k = i >> 7, c = i & 127;
            Wsh[i] = W1[(k0 + k) * 128 + c];
        }
        __syncthreads();
#pragma unroll 4
        for (int k = 0; k < 64; k++) {
            unsigned long long p[4];
#pragma unroll
            for (int r = 0; r < 4; r++) {
                float a = Hs[(ty * 4 + r) * 128 + k0 + k];
                p[r] = packf2(a, a);
            }
            const ulonglong2* wp = (const ulonglong2*)&Wsh[k * 128 + tx * 8];
            ulonglong2 wA = wp[0], wB = wp[1];
#pragma unroll
            for (int r = 0; r < 4; r++) {
                acc[r][0] = ffma2(p[r], wA.x, acc[r][0]);
                acc[r][1] = ffma2(p[r], wA.y, acc[r][1]);
                acc[r][2] = ffma2(p[r], wB.x, acc[r][2]);
                acc[r][3] = ffma2(p[r], wB.y, acc[r][3]);
            }
        }
        __syncthreads();
    }
#pragma unroll
    for (int r = 0; r < 4; r++) {
        float out[8];
#pragma unroll
        for (int c = 0; c < 4; c++) {
            float2 u = unpackf2(acc[r][c]);
            out[2 * c] = u.x;
            out[2 * c + 1] = u.y;
        }
        float4* cp = (float4*)&C[(long long)(row0 + ty * 4 + r) * 128 + col0];
        cp[0] = make_float4(out[0], out[1], out[2], out[3]);
        cp[1] = make_float4(out[4], out[5], out[6], out[7]);
    }
}

// ================= plain GEMM (levels 1,2): C = A @ W =====================
__global__ __launch_bounds__(256) void k_gemm(const float* __restrict__ A,
                                              const float* __restrict__ W,
                                              float* __restrict__ C) {
    __shared__ float Ash[64 * 64];
    __shared__ float Wsh[64 * 128];
    const int tid = threadIdx.x;
    const int tx = tid & 15, ty = tid >> 4;
    const int row0 = blockIdx.x * 64;

    unsigned long long acc[4][4];
#pragma unroll
    for (int r = 0; r < 4; r++)
#pragma unroll
        for (int c = 0; c < 4; c++) acc[r][c] = 0ull;

#pragma unroll
    for (int k0 = 0; k0 < 128; k0 += 64) {
        for (int i = tid; i < 64 * 64; i += 256) {
            int r = i >> 6, k = i & 63;
            Ash[i] = A[(long long)(row0 + r) * 128 + k0 + k];
        }
        for (int i = tid; i < 64 * 128; i += 256) {
            int k = i >> 7, c = i & 127;
            Wsh[i] = W[(k0 + k) * 128 + c];
        }
        __syncthreads();
#pragma unroll 4
        for (int k = 0; k < 64; k++) {
            unsigned long long p[4];
#pragma unroll
            for (int r = 0; r < 4; r++) {
                float a = Ash[(ty * 4 + r) * 64 + k];
                p[r] = packf2(a, a);
            }
            const ulonglong2* wp = (const ulonglong2*)&Wsh[k * 128 + tx * 8];
            ulonglong2 wA = wp[0], wB = wp[1];
#pragma unroll
            for (int r = 0; r < 4; r++) {
                acc[r][0] = ffma2(p[r], wA.x, acc[r][0]);
                acc[r][1] = ffma2(p[r], wA.y, acc[r][1]);
                acc[r][2] = ffma2(p[r], wB.x, acc[r][2]);
                acc[r][3] = ffma2(p[r], wB.y, acc[r][3]);
            }
        }
        __syncthreads();
    }
    const int col0 = tx * 8;
#pragma unroll
    for (int r = 0; r < 4; r++) {
        float out[8];
#pragma unroll
        for (int c = 0; c < 4; c++) {
            float2 u = unpackf2(acc[r][c]);
            out[2 * c] = u.x;
            out[2 * c + 1] = u.y;
        }
        float4* cp = (float4*)&C[(long long)(row0 + ty * 4 + r) * 128 + col0];
        cp[0] = make_float4(out[0], out[1], out[2], out[3]);
        cp[1] = make_float4(out[4], out[5], out[6], out[7]);
    }
}

// ================= conv: quarter-channel smem gather + fused BN stats =====
// grid (NG, 4), 512 threads, dynamic smem = nper*32 floats
__global__ __launch_bounds__(512) void k_conv(const float* __restrict__ xl,
                                              float* __restrict__ out,
                                              const float* __restrict__ bias,
                                              int nper, int lvl) {
    extern __shared__ float sf[];
    __shared__ float sred[1024];
    const int g = blockIdx.x, q = blockIdx.y;
    const int t = threadIdx.x, wid = t >> 5, lane = t & 31;
    const long long rb = (long long)g * nper;

    for (int idx = t; idx < nper * 8; idx += 512) {
        int r = idx >> 3, c4 = idx & 7;
        ((float4*)sf)[r * 8 + c4] = ((const float4*)(xl + (rb + r) * 128 + q * 32))[c4];
    }
    __syncthreads();

    const int ch = q * 32 + lane;
    const float bb = bias[ch];
    float bs = 0.f, bq = 0.f;
    for (int node = wid; node < nper; node += 16) {
        int gnode = (g << 9) + node;
        int base = d_coff[gnode];
        int cnt = d_indeg[gnode];
        float a = 0.f;
#pragma unroll 4
        for (int j = 0; j < cnt; j++) {
            long long ll = __ldg(&d_csr[base + j]);
            int sl = (int)(ll & 0xffffffffll);
            float w = __int_as_float((int)(ll >> 32));
            a += w * sf[sl * 32 + lane];
        }
        float di = d_dinv[gnode];
        a += di * di * sf[node * 32 + lane] + bb;
        out[(rb + node) * 128 + ch] = a;
        bs += a;
        bq += a * a;
    }
    sred[wid * 32 + lane] = bs;
    sred[512 + wid * 32 + lane] = bq;
    __syncthreads();
    if (t < 32) {
        float s = 0.f, s2 = 0.f;
#pragma unroll
        for (int w = 0; w < 16; w++) {
            s += sred[w * 32 + t];
            s2 += sred[512 + w * 32 + t];
        }
        atomicAdd(&d_bnsum3[lvl][q * 32 + t], s);
        atomicAdd(&d_bnsq3[lvl][q * 32 + t], s2);
    }
}

// ========== mega topk: BN + score + sort + gather + readout + remap + scan + fill ==========
__global__ __launch_bounds__(1024) void k_topk(const float* __restrict__ X,
                                               float* __restrict__ newh,
                                               const float* __restrict__ gamma,
                                               const float* __restrict__ beta,
                                               const float* __restrict__ att,
                                               int nper, int k, int ntot, int lvl,
                                               int do_remap) {
    extern __shared__ int rk[];  // EPG ints
    __shared__ float sscale[128], sshift[128], satt[128];
    __shared__ float score[512];
    __shared__ unsigned long long key[512];
    __shared__ short klocal[512];
    __shared__ float ksc[512];
    __shared__ float red[2048];
    __shared__ int o2n[512];
    __shared__ int scnt[512];
    __shared__ float dv[512];
    __shared__ int wtmp[16], wexcl[16];
    const int g = blockIdx.x, t = threadIdx.x, wid = t >> 5, lane = t & 31;

    if (t < 128) {
        float inv_n = 1.f / (float)ntot;
        float mu = d_bnsum3[lvl][t] * inv_n;
        float var = d_bnsq3[lvl][t] * inv_n - mu * mu;
        float sc = gamma[t] * rsqrtf(var + BN_EPS);
        sscale[t] = sc;
        sshift[t] = beta[t] - mu * sc;
        satt[t] = att[t];
    }
    if (t < 512) { o2n[t] = -1; scnt[t] = 0; }
    __syncthreads();

    const long long rb = (long long)g * nper;
    const float ainv = d_attinv3[lvl];
    for (int node = wid; node < nper; node += 32) {
        float4 v = ((const float4*)(X + (rb + node) * 128))[lane];
        int c = lane * 4;
        float h0 = fmaxf(fmaf(v.x, sscale[c], sshift[c]), 0.f);
        float h1 = fmaxf(fmaf(v.y, sscale[c + 1], sshift[c + 1]), 0.f);
        float h2 = fmaxf(fmaf(v.z, sscale[c + 2], sshift[c + 2]), 0.f);
        float h3 = fmaxf(fmaf(v.w, sscale[c + 3], sshift[c + 3]), 0.f);
        float dot = h0 * satt[c] + h1 * satt[c + 1] + h2 * satt[c + 2] + h3 * satt[c + 3];
#pragma unroll
        for (int o = 16; o > 0; o >>= 1) dot += __shfl_xor_sync(0xffffffffu, dot, o);
        if (lane == 0) score[node] = tanhf(dot * ainv);
    }
    __syncthreads();

    if (t < 512) {
        unsigned long long kk = 0xFFFFFFFFFFFFFFFFull;
        if (t < nper) {
            unsigned fu = __float_as_uint(score[t]);
            unsigned asc = (fu & 0x80000000u) ? ~fu : (fu | 0x80000000u);
            kk = ((unsigned long long)(~asc) << 32) | (unsigned)t;
        }
        key[t] = kk;
    }
    __syncthreads();
    for (int sz = 2; sz <= 512; sz <<= 1) {
        for (int j = sz >> 1; j > 0; j >>= 1) {
            if (t < 512) {
                int ixj = t ^ j;
                if (ixj > t) {
                    bool up = ((t & sz) == 0);
                    unsigned long long a = key[t], b = key[ixj];
                    if ((a > b) == up) {
                        key[t] = b;
                        key[ixj] = a;
                    }
                }
            }
            __syncthreads();
        }
    }
    if (t < k) {
        int local = (int)(unsigned)(key[t] & 0xffffffffull);
        o2n[local] = t;
        klocal[t] = (short)local;
        ksc[t] = score[local];
    }
    __syncthreads();

    // gather + gate + readout
    const int c = t & 127;
    const float sc = sscale[c], sh = sshift[c];
    float mx = -3.4e38f, sm = 0.f;
    for (int j = t >> 7; j < k; j += 8) {
        float raw = X[(rb + klocal[j]) * 128 + c];
        float val = fmaxf(fmaf(raw, sc, sh), 0.f) * ksc[j];
        if (do_remap) newh[((long long)(g * k + j)) * 128 + c] = val;
        mx = fmaxf(mx, val);
        sm += val;
    }
    red[t] = mx;
    red[1024 + t] = sm;
    __syncthreads();
    if (t < 128) {
        float m = red[t], s = red[1024 + t];
#pragma unroll
        for (int i = 1; i < 8; i++) {
            m = fmaxf(m, red[t + 128 * i]);
            s += red[1024 + t + 128 * i];
        }
        float* o = d_read + lvl * NG * 256 + g * 256;
        o[t] = m;
        o[128 + t] = s / (float)k;
    }
    if (!do_remap) return;

    // ---- remap edges + count next-level in-degrees (smem atomics) ----
    const int e0 = g * EPG;
    for (int i = t; i < EPG; i += 1024) {
        int r = -1;
        if (d_em[e0 + i]) {
            int s2 = o2n[d_srcE[e0 + i]];
            int d2 = o2n[d_dstE[e0 + i]];
            if (s2 >= 0 && d2 >= 0) {
                r = atomicAdd(&scnt[d2], 1);
                d_srcE[e0 + i] = s2;
                d_dstE[e0 + i] = d2;
            } else {
                d_em[e0 + i] = 0;
            }
        }
        rk[i] = r;
    }
    __syncthreads();

    // ---- scan k counts -> offsets, dinv ----
    int v = 0;
    if (t < 512) v = (t < k) ? scnt[t] : 0;
    int incl = v;
#pragma unroll
    for (int o = 1; o < 32; o <<= 1) {
        int y = __shfl_up_sync(0xffffffffu, incl, o);
        if (lane >= o) incl += y;
    }
    if (t < 512 && lane == 31) wtmp[wid] = incl;
    __syncthreads();
    if (t < 16) {
        int w = wtmp[t], s = w;
#pragma unroll
        for (int o = 1; o < 16; o <<= 1) {
            int y = __shfl_up_sync(0x0000ffffu, s, o);
            if (t >= o) s += y;
        }
        wexcl[t] = s - w;
    }
    __syncthreads();
    if (t < 512) {
        int excl = incl - v + wexcl[wid];
        if (t < k) {
            int node = (g << 9) + t;
            d_coff[node] = e0 + excl;
            d_indeg[node] = v;
            float di = rsqrtf((float)v + 1.f);
            d_dinv[node] = di;
            dv[t] = di;
            scnt[t] = excl;
        }
    }
    __syncthreads();

    // ---- fill CSR (atomic-free) ----
    for (int i = t; i < EPG; i += 1024) {
        if (rk[i] >= 0) {
            int s2 = d_srcE[e0 + i], d2 = d_dstE[e0 + i];
            union { struct { int s; float c; } p; long long ll; } u;
            u.p.s = s2;
            u.p.c = dv[s2] * dv[d2];
            d_csr[e0 + scnt[d2] + rk[i]] = u.ll;
        }
    }
}

// ================= final MLP =================
__global__ __launch_bounds__(128) void k_final(const float* __restrict__ Wl1,
                                               const float* __restrict__ bl1,
                                               const float* __restrict__ Wl2,
                                               const float* __restrict__ bl2,
                                               float* __restrict__ out) {
    __shared__ float s[256];
    __shared__ float hid[128];
    int g = blockIdx.x, t = threadIdx.x;
    for (int i = t; i < 256; i += 128)
        s[i] = d_read[0 * NG * 256 + g * 256 + i] + d_read[1 * NG * 256 + g * 256 + i] +
               d_read[2 * NG * 256 + g * 256 + i];
    __syncthreads();
    float acc = bl1[t];
#pragma unroll 8
    for (int j = 0; j < 256; j++) acc += s[j] * Wl1[j * 128 + t];
    hid[t] = fmaxf(acc, 0.f);
    __syncthreads();
    if (t < 64) {
        int o = t >> 5, lane = t & 31;
        float p = 0.f;
#pragma unroll
        for (int j = lane; j < 128; j += 32) p += hid[j] * Wl2[j * 2 + o];
#pragma unroll
        for (int off = 16; off > 0; off >>= 1) p += __shfl_xor_sync(0xffffffffu, p, off);
        if (lane == 0) out[g * 2 + o] = p + bl2[o];
    }
}

// ================= orchestration =================
extern "C" void kernel_launch(void* const* d_in, const int* in_sizes, int n_in,
                              void* d_out, int out_size) {
    (void)in_sizes; (void)n_in; (void)out_size;
    const float* x = (const float*)d_in[0];
    const int* ei = (const int*)d_in[1];
    const float* Wp = (const float*)d_in[3];
    const float* bp = (const float*)d_in[4];
    const float* Wc[3] = {(const float*)d_in[5], (const float*)d_in[10], (const float*)d_in[15]};
    const float* bc[3] = {(const float*)d_in[6], (const float*)d_in[11], (const float*)d_in[16]};
    const float* gc[3] = {(const float*)d_in[7], (const float*)d_in[12], (const float*)d_in[17]};
    const float* be[3] = {(const float*)d_in[8], (const float*)d_in[13], (const float*)d_in[18]};
    const float* at[3] = {(const float*)d_in[9], (const float*)d_in[14], (const float*)d_in[19]};
    const float* Wl1 = (const float*)d_in[20];
    const float* bl1 = (const float*)d_in[21];
    const float* Wl2 = (const float*)d_in[22];
    const float* bl2 = (const float*)d_in[23];

    float *bufA, *bufB;
    cudaGetSymbolAddress((void**)&bufA, d_bufA);
    cudaGetSymbolAddress((void**)&bufB, d_bufB);

    // Opt-in smem limits (idempotent; k_topk needs the opt-in because its
    // static 25KB + dynamic 32KB exceeds the default 48KB combined cap).
    cudaFuncSetAttribute(k_gemm2, cudaFuncAttributeMaxDynamicSharedMemorySize, 81920);
    cudaFuncSetAttribute(k_conv, cudaFuncAttributeMaxDynamicSharedMemorySize, 65536);
    cudaFuncSetAttribute(k_topk, cudaFuncAttributeMaxDynamicSharedMemorySize, 40960);

    k_init<<<NG, 512>>>(ei, at[0], at[1], at[2]);
    k_gemm2<<<N0TOT / 64, 256, 81920>>>(x, Wp, bp, Wc[0], bufB);
    k_conv<<<dim3(NG, 4), 512, NPER0 * 32 * sizeof(float)>>>(bufB, bufA, bc[0], NPER0, 0);
    k_topk<<<NG, 1024, EPG * sizeof(int)>>>(bufA, bufB, gc[0], be[0], at[0],
                                            NPER0, K1C, N0TOT, 0, 1);
    k_gemm<<<N1TOT / 64, 256>>>(bufB, Wc[1], bufA);
    k_conv<<<dim3(NG, 4), 512, K1C * 32 * sizeof(float)>>>(bufA, bufB, bc[1], K1C, 1);
    k_topk<<<NG, 1024, EPG * sizeof(int)>>>(bufB, bufA, gc[1], be[1], at[1],
                                            K1C, K2C, N1TOT, 1, 1);
    k_gemm<<<N2TOT / 64, 256>>>(bufA, Wc[2], bufB);
    k_conv<<<dim3(NG, 4), 512, K2C * 32 * sizeof(float)>>>(bufB, bufA, bc[2], K2C, 2);
    k_topk<<<NG, 1024, EPG * sizeof(int)>>>(bufA, bufB, gc[2], be[2], at[2],
                                            K2C, K3C, N2TOT, 2, 0);
    k_final<<<NG, 128>>>(Wl1, bl1, Wl2, bl2, (float*)d_out);
}

// round 14
// speedup vs baseline: 1.5646x; 1.4127x over previous
#include <cuda_runtime.h>
#include <cuda_bf16.h>
#include <cstdint>

#define NG 128
#define NPER0 512
#define N0TOT 65536
#define E_TOT 1048576
#define EPG 8192
#define INC 100
#define HIDC 128
#define K1C 410
#define K2C 328
#define K3C 263
#define N1TOT (NG*K1C)
#define N2TOT (NG*K2C)
#define BN_EPS 1e-5f

#define LDB 136            // bf16 units per smem row (pad: conflict-free fragments)
#define TILE_ELEMS (128*LDB)
#define MM_SMEM (4*TILE_ELEMS*2)   // 4 bf16 tiles = 139264 B

// ---------------- device scratch ----------------
__device__ __align__(16) float d_bufA[N0TOT*HIDC];
__device__ __align__(16) float d_bufB[N0TOT*HIDC];
__device__ int   d_indeg[NG*NPER0];
__device__ int   d_coff[NG*NPER0];
__device__ float d_dinv[NG*NPER0];
__device__ int   d_srcE[E_TOT];
__device__ int   d_dstE[E_TOT];
__device__ unsigned char d_em[E_TOT];
__device__ long long d_csr[E_TOT];
__device__ __align__(16) float d_bnsum3[3][HIDC];
__device__ __align__(16) float d_bnsq3[3][HIDC];
__device__ float d_attinv3[3];
__device__ __align__(16) float d_read[3*NG*2*HIDC];

// ---------------- mma.sync bf16 helper (sm_80+, valid on sm_103) ----------------
__device__ __forceinline__ void mma_bf16(float* d, const uint32_t* a, const uint32_t* b) {
    asm volatile(
        "mma.sync.aligned.m16n8k16.row.col.f32.bf16.bf16.f32 "
        "{%0,%1,%2,%3},{%4,%5,%6,%7},{%8,%9},{%0,%1,%2,%3};"
        : "+f"(d[0]), "+f"(d[1]), "+f"(d[2]), "+f"(d[3])
        : "r"(a[0]), "r"(a[1]), "r"(a[2]), "r"(a[3]), "r"(b[0]), "r"(b[1]));
}
__device__ __forceinline__ uint32_t pack_hi(float x, float y) {
    __nv_bfloat162 p = __floats2bfloat162_rn(x, y);
    return *(uint32_t*)&p;
}

// frag compute core: acc[16][4] over warp tile 64x32, K-steps [0, nk16)
__device__ __forceinline__ void mm_core(const __nv_bfloat16* Ah, const __nv_bfloat16* Al,
                                        const __nv_bfloat16* Bh, const __nv_bfloat16* Bl,
                                        int mw, int nw, int g, int tg, int nk16,
                                        float acc[16][4]) {
#pragma unroll
    for (int pass = 0; pass < 3; pass++) {
        const __nv_bfloat16* As = (pass == 2) ? Al : Ah;
        const __nv_bfloat16* Bs = (pass == 1) ? Bl : Bh;
        for (int ks = 0; ks < nk16; ks++) {
            const int kb = ks * 16 + tg * 2;
            uint32_t a[4][4], b[4][2];
#pragma unroll
            for (int mt = 0; mt < 4; mt++) {
                int r = mw + mt * 16 + g;
                a[mt][0] = *(const uint32_t*)&As[r * LDB + kb];
                a[mt][1] = *(const uint32_t*)&As[(r + 8) * LDB + kb];
                a[mt][2] = *(const uint32_t*)&As[r * LDB + kb + 8];
                a[mt][3] = *(const uint32_t*)&As[(r + 8) * LDB + kb + 8];
            }
#pragma unroll
            for (int nt = 0; nt < 4; nt++) {
                int n = nw + nt * 8 + g;
                b[nt][0] = *(const uint32_t*)&Bs[n * LDB + kb];
                b[nt][1] = *(const uint32_t*)&Bs[n * LDB + kb + 8];
            }
#pragma unroll
            for (int mt = 0; mt < 4; mt++)
#pragma unroll
                for (int nt = 0; nt < 4; nt++) mma_bf16(acc[mt * 4 + nt], a[mt], b[nt]);
        }
    }
}

// ================= plain GEMM (K=128): C[M,128] = A[M,128] @ W[128,128] ==========
__global__ __launch_bounds__(256) void k_mm(const float* __restrict__ A,
                                            const float* __restrict__ W,
                                            float* __restrict__ C) {
    extern __shared__ char sm[];
    __nv_bfloat16* Ah = (__nv_bfloat16*)sm;
    __nv_bfloat16* Al = Ah + TILE_ELEMS;
    __nv_bfloat16* Bh = Al + TILE_ELEMS;
    __nv_bfloat16* Bl = Bh + TILE_ELEMS;
    const int t = threadIdx.x, w = t >> 5, lane = t & 31, g = lane >> 2, tg = lane & 3;
    const long long row0 = (long long)blockIdx.x * 128;

    for (int i = t; i < 128 * 64; i += 256) {
        int r = i >> 6, k2 = (i & 63) * 2;
        float2 v = *(const float2*)&A[(row0 + r) * 128 + k2];
        __nv_bfloat16 hx = __float2bfloat16(v.x), hy = __float2bfloat16(v.y);
        *(uint32_t*)&Ah[r * LDB + k2] = pack_hi(v.x, v.y);
        *(uint32_t*)&Al[r * LDB + k2] =
            pack_hi(v.x - __bfloat162float(hx), v.y - __bfloat162float(hy));
    }
    for (int i = t; i < 128 * 128; i += 256) {
        int k = i >> 7, n = i & 127;
        float v = W[i];
        __nv_bfloat16 h = __float2bfloat16(v);
        Bh[n * LDB + k] = h;
        Bl[n * LDB + k] = __float2bfloat16(v - __bfloat162float(h));
    }
    __syncthreads();

    const int mw = (w & 1) * 64, nw = (w >> 1) * 32;
    float acc[16][4];
#pragma unroll
    for (int i = 0; i < 16; i++)
#pragma unroll
        for (int j = 0; j < 4; j++) acc[i][j] = 0.f;

    mm_core(Ah, Al, Bh, Bl, mw, nw, g, tg, 8, acc);

#pragma unroll
    for (int mt = 0; mt < 4; mt++)
#pragma unroll
        for (int nt = 0; nt < 4; nt++) {
            long long r = row0 + mw + mt * 16 + g;
            int c = nw + nt * 8 + tg * 2;
            float* ap = acc[mt * 4 + nt];
            *(float2*)&C[r * 128 + c] = make_float2(ap[0], ap[1]);
            *(float2*)&C[(r + 8) * 128 + c] = make_float2(ap[2], ap[3]);
        }
}

// ====== fused: h = relu(x@Wp + bp); C = h @ W1  (K phase A padded 100->112) ======
__global__ __launch_bounds__(256) void k_mm2(const float* __restrict__ X,
                                             const float* __restrict__ Wp,
                                             const float* __restrict__ bp,
                                             const float* __restrict__ W1,
                                             float* __restrict__ C) {
    extern __shared__ char sm[];
    __nv_bfloat16* Ah = (__nv_bfloat16*)sm;
    __nv_bfloat16* Al = Ah + TILE_ELEMS;
    __nv_bfloat16* Bh = Al + TILE_ELEMS;
    __nv_bfloat16* Bl = Bh + TILE_ELEMS;
    __shared__ float sbias[128];
    const int t = threadIdx.x, w = t >> 5, lane = t & 31, g = lane >> 2, tg = lane & 3;
    const long long row0 = (long long)blockIdx.x * 128;

    if (t < 128) sbias[t] = bp[t];
    // zero pad region k in [96,112) of all 4 tiles
    for (int i = t; i < 128 * 16; i += 256) {
        int r = i >> 4, k = 96 + (i & 15);
        Ah[r * LDB + k] = __nv_bfloat16(0.f);
        Al[r * LDB + k] = __nv_bfloat16(0.f);
        Bh[r * LDB + k] = __nv_bfloat16(0.f);
        Bl[r * LDB + k] = __nv_bfloat16(0.f);
    }
    __syncthreads();
    for (int i = t; i < 128 * 50; i += 256) {   // x: 128 rows x 100 cols (50 float2)
        int r = i / 50, k2 = (i - r * 50) * 2;
        float2 v = *(const float2*)&X[(row0 + r) * INC + k2];
        __nv_bfloat16 hx = __float2bfloat16(v.x), hy = __float2bfloat16(v.y);
        *(uint32_t*)&Ah[r * LDB + k2] = pack_hi(v.x, v.y);
        *(uint32_t*)&Al[r * LDB + k2] =
            pack_hi(v.x - __bfloat162float(hx), v.y - __bfloat162float(hy));
    }
    for (int i = t; i < INC * 128; i += 256) {
        int k = i >> 7, n = i & 127;
        float v = Wp[i];
        __nv_bfloat16 h = __float2bfloat16(v);
        Bh[n * LDB + k] = h;
        Bl[n * LDB + k] = __float2bfloat16(v - __bfloat162float(h));
    }
    __syncthreads();

    const int mw = (w & 1) * 64, nw = (w >> 1) * 32;
    float acc[16][4];
#pragma unroll
    for (int i = 0; i < 16; i++)
#pragma unroll
        for (int j = 0; j < 4; j++) acc[i][j] = 0.f;

    mm_core(Ah, Al, Bh, Bl, mw, nw, g, tg, 7, acc);   // 112/16 = 7 ksteps
    __syncthreads();   // all smem reads done before overwrite

    // bias+relu, split h -> Ah/Al (k index = output col); then load W1 -> Bh/Bl
#pragma unroll
    for (int mt = 0; mt < 4; mt++)
#pragma unroll
        for (int nt = 0; nt < 4; nt++) {
            int r = mw + mt * 16 + g;
            int c = nw + nt * 8 + tg * 2;
            float* ap = acc[mt * 4 + nt];
            float v0 = fmaxf(ap[0] + sbias[c], 0.f);
            float v1 = fmaxf(ap[1] + sbias[c + 1], 0.f);
            float v2 = fmaxf(ap[2] + sbias[c], 0.f);
            float v3 = fmaxf(ap[3] + sbias[c + 1], 0.f);
            __nv_bfloat16 h0 = __float2bfloat16(v0), h1 = __float2bfloat16(v1);
            __nv_bfloat16 h2 = __float2bfloat16(v2), h3 = __float2bfloat16(v3);
            *(uint32_t*)&Ah[r * LDB + c] = pack_hi(v0, v1);
            *(uint32_t*)&Al[r * LDB + c] =
                pack_hi(v0 - __bfloat162float(h0), v1 - __bfloat162float(h1));
            *(uint32_t*)&Ah[(r + 8) * LDB + c] = pack_hi(v2, v3);
            *(uint32_t*)&Al[(r + 8) * LDB + c] =
                pack_hi(v2 - __bfloat162float(h2), v3 - __bfloat162float(h3));
            ap[0] = ap[1] = ap[2] = ap[3] = 0.f;
        }
    for (int i = t; i < 128 * 128; i += 256) {
        int k = i >> 7, n = i & 127;
        float v = W1[i];
        __nv_bfloat16 h = __float2bfloat16(v);
        Bh[n * LDB + k] = h;
        Bl[n * LDB + k] = __float2bfloat16(v - __bfloat162float(h));
    }
    __syncthreads();

    mm_core(Ah, Al, Bh, Bl, mw, nw, g, tg, 8, acc);

#pragma unroll
    for (int mt = 0; mt < 4; mt++)
#pragma unroll
        for (int nt = 0; nt < 4; nt++) {
            long long r = row0 + mw + mt * 16 + g;
            int c = nw + nt * 8 + tg * 2;
            float* ap = acc[mt * 4 + nt];
            *(float2*)&C[r * 128 + c] = make_float2(ap[0], ap[1]);
            *(float2*)&C[(r + 8) * 128 + c] = make_float2(ap[2], ap[3]);
        }
}

// ================= init: edge load + count + scan + CSR fill (level 0) ===========
__global__ __launch_bounds__(512) void k_init(const int* __restrict__ ei,
                                              const float* __restrict__ at0,
                                              const float* __restrict__ at1,
                                              const float* __restrict__ at2) {
    __shared__ int scnt[512];
    __shared__ int rk[EPG];
    __shared__ float dv[512];
    __shared__ int wtmp[16], wexcl[16];
    const int g = blockIdx.x, t = threadIdx.x, lane = t & 31, wid = t >> 5;
    scnt[t] = 0;
    if (g == 0) {
        if (t < 384) {
            ((float*)d_bnsum3)[t] = 0.f;
            ((float*)d_bnsq3)[t] = 0.f;
        }
        if (wid >= 13) {
            const float* ap = (wid == 13) ? at0 : (wid == 14) ? at1 : at2;
            float s = 0.f;
#pragma unroll
            for (int q = 0; q < 4; q++) { float v = ap[lane + 32 * q]; s += v * v; }
#pragma unroll
            for (int o = 16; o > 0; o >>= 1) s += __shfl_xor_sync(0xffffffffu, s, o);
            if (lane == 0) d_attinv3[wid - 13] = rsqrtf(s);
        }
    }
    __syncthreads();
    const int e0 = g * EPG;
    for (int i = t; i < EPG; i += 512) {
        int sl = ei[e0 + i] - (g << 9);
        int dl = ei[E_TOT + e0 + i] - (g << 9);
        rk[i] = atomicAdd(&scnt[dl], 1);
        d_srcE[e0 + i] = sl;
        d_dstE[e0 + i] = dl;
        d_em[e0 + i] = 1;
    }
    __syncthreads();
    int v = scnt[t];
    int incl = v;
#pragma unroll
    for (int o = 1; o < 32; o <<= 1) {
        int y = __shfl_up_sync(0xffffffffu, incl, o);
        if (lane >= o) incl += y;
    }
    if (lane == 31) wtmp[wid] = incl;
    __syncthreads();
    if (t < 16) {
        int w = wtmp[t], s = w;
#pragma unroll
        for (int o = 1; o < 16; o <<= 1) {
            int y = __shfl_up_sync(0x0000ffffu, s, o);
            if (t >= o) s += y;
        }
        wexcl[t] = s - w;
    }
    __syncthreads();
    int excl = incl - v + wexcl[wid];
    {
        int node = (g << 9) + t;
        d_coff[node] = e0 + excl;
        d_indeg[node] = v;
        float di = rsqrtf((float)v + 1.f);
        d_dinv[node] = di;
        dv[t] = di;
        scnt[t] = excl;
    }
    __syncthreads();
    for (int i = t; i < EPG; i += 512) {
        int sl = d_srcE[e0 + i], dl = d_dstE[e0 + i];
        int slot = scnt[dl] + rk[i];
        union { struct { int s; float c; } p; long long ll; } u;
        u.p.s = sl;
        u.p.c = dv[sl] * dv[dl];
        d_csr[e0 + slot] = u.ll;
    }
}

// ================= conv: quarter-channel smem gather + fused BN stats =====
__global__ __launch_bounds__(512) void k_conv(const float* __restrict__ xl,
                                              float* __restrict__ out,
                                              const float* __restrict__ bias,
                                              int nper, int lvl) {
    extern __shared__ float sf[];
    __shared__ float sred[1024];
    const int g = blockIdx.x, q = blockIdx.y;
    const int t = threadIdx.x, wid = t >> 5, lane = t & 31;
    const long long rb = (long long)g * nper;

    for (int idx = t; idx < nper * 8; idx += 512) {
        int r = idx >> 3, c4 = idx & 7;
        ((float4*)sf)[r * 8 + c4] = ((const float4*)(xl + (rb + r) * 128 + q * 32))[c4];
    }
    __syncthreads();

    const int ch = q * 32 + lane;
    const float bb = bias[ch];
    float bs = 0.f, bq = 0.f;
    for (int node = wid; node < nper; node += 16) {
        int gnode = (g << 9) + node;
        int base = d_coff[gnode];
        int cnt = d_indeg[gnode];
        float a = 0.f;
#pragma unroll 4
        for (int j = 0; j < cnt; j++) {
            long long ll = __ldg(&d_csr[base + j]);
            int sl = (int)(ll & 0xffffffffll);
            float w = __int_as_float((int)(ll >> 32));
            a += w * sf[sl * 32 + lane];
        }
        float di = d_dinv[gnode];
        a += di * di * sf[node * 32 + lane] + bb;
        out[(rb + node) * 128 + ch] = a;
        bs += a;
        bq += a * a;
    }
    sred[wid * 32 + lane] = bs;
    sred[512 + wid * 32 + lane] = bq;
    __syncthreads();
    if (t < 32) {
        float s = 0.f, s2 = 0.f;
#pragma unroll
        for (int w = 0; w < 16; w++) {
            s += sred[w * 32 + t];
            s2 += sred[512 + w * 32 + t];
        }
        atomicAdd(&d_bnsum3[lvl][q * 32 + t], s);
        atomicAdd(&d_bnsq3[lvl][q * 32 + t], s2);
    }
}

// ========== mega topk: BN + score + sort + gather + readout + remap + scan + fill ==========
__global__ __launch_bounds__(1024) void k_topk(const float* __restrict__ X,
                                               float* __restrict__ newh,
                                               const float* __restrict__ gamma,
                                               const float* __restrict__ beta,
                                               const float* __restrict__ att,
                                               int nper, int k, int ntot, int lvl,
                                               int do_remap) {
    extern __shared__ int rk[];  // EPG ints
    __shared__ float sscale[128], sshift[128], satt[128];
    __shared__ float score[512];
    __shared__ unsigned long long key[512];
    __shared__ short klocal[512];
    __shared__ float ksc[512];
    __shared__ float red[2048];
    __shared__ int o2n[512];
    __shared__ int scnt[512];
    __shared__ float dv[512];
    __shared__ int wtmp[16], wexcl[16];
    const int g = blockIdx.x, t = threadIdx.x, wid = t >> 5, lane = t & 31;

    if (t < 128) {
        float inv_n = 1.f / (float)ntot;
        float mu = d_bnsum3[lvl][t] * inv_n;
        float var = d_bnsq3[lvl][t] * inv_n - mu * mu;
        float sc = gamma[t] * rsqrtf(var + BN_EPS);
        sscale[t] = sc;
        sshift[t] = beta[t] - mu * sc;
        satt[t] = att[t];
    }
    if (t < 512) { o2n[t] = -1; scnt[t] = 0; }
    __syncthreads();

    const long long rb = (long long)g * nper;
    const float ainv = d_attinv3[lvl];
    for (int node = wid; node < nper; node += 32) {
        float4 v = ((const float4*)(X + (rb + node) * 128))[lane];
        int c = lane * 4;
        float h0 = fmaxf(fmaf(v.x, sscale[c], sshift[c]), 0.f);
        float h1 = fmaxf(fmaf(v.y, sscale[c + 1], sshift[c + 1]), 0.f);
        float h2 = fmaxf(fmaf(v.z, sscale[c + 2], sshift[c + 2]), 0.f);
        float h3 = fmaxf(fmaf(v.w, sscale[c + 3], sshift[c + 3]), 0.f);
        float dot = h0 * satt[c] + h1 * satt[c + 1] + h2 * satt[c + 2] + h3 * satt[c + 3];
#pragma unroll
        for (int o = 16; o > 0; o >>= 1) dot += __shfl_xor_sync(0xffffffffu, dot, o);
        if (lane == 0) score[node] = tanhf(dot * ainv);
    }
    __syncthreads();

    if (t < 512) {
        unsigned long long kk = 0xFFFFFFFFFFFFFFFFull;
        if (t < nper) {
            unsigned fu = __float_as_uint(score[t]);
            unsigned asc = (fu & 0x80000000u) ? ~fu : (fu | 0x80000000u);
            kk = ((unsigned long long)(~asc) << 32) | (unsigned)t;
        }
        key[t] = kk;
    }
    __syncthreads();
    for (int sz = 2; sz <= 512; sz <<= 1) {
        for (int j = sz >> 1; j > 0; j >>= 1) {
            if (t < 512) {
                int ixj = t ^ j;
                if (ixj > t) {
                    bool up = ((t & sz) == 0);
                    unsigned long long a = key[t], b = key[ixj];
                    if ((a > b) == up) {
                        key[t] = b;
                        key[ixj] = a;
                    }
                }
            }
            __syncthreads();
        }
    }
    if (t < k) {
        int local = (int)(unsigned)(key[t] & 0xffffffffull);
        o2n[local] = t;
        klocal[t] = (short)local;
        ksc[t] = score[local];
    }
    __syncthreads();

    const int c = t & 127;
    const float sc = sscale[c], sh = sshift[c];
    float mx = -3.4e38f, sm = 0.f;
    for (int j = t >> 7; j < k; j += 8) {
        float raw = X[(rb + klocal[j]) * 128 + c];
        float val = fmaxf(fmaf(raw, sc, sh), 0.f) * ksc[j];
        if (do_remap) newh[((long long)(g * k + j)) * 128 + c] = val;
        mx = fmaxf(mx, val);
        sm += val;
    }
    red[t] = mx;
    red[1024 + t] = sm;
    __syncthreads();
    if (t < 128) {
        float m = red[t], s = red[1024 + t];
#pragma unroll
        for (int i = 1; i < 8; i++) {
            m = fmaxf(m, red[t + 128 * i]);
            s += red[1024 + t + 128 * i];
        }
        float* o = d_read + lvl * NG * 256 + g * 256;
        o[t] = m;
        o[128 + t] = s / (float)k;
    }
    if (!do_remap) return;

    const int e0 = g * EPG;
    for (int i = t; i < EPG; i += 1024) {
        int r = -1;
        if (d_em[e0 + i]) {
            int s2 = o2n[d_srcE[e0 + i]];
            int d2 = o2n[d_dstE[e0 + i]];
            if (s2 >= 0 && d2 >= 0) {
                r = atomicAdd(&scnt[d2], 1);
                d_srcE[e0 + i] = s2;
                d_dstE[e0 + i] = d2;
            } else {
                d_em[e0 + i] = 0;
            }
        }
        rk[i] = r;
    }
    __syncthreads();

    int v = 0;
    if (t < 512) v = (t < k) ? scnt[t] : 0;
    int incl = v;
#pragma unroll
    for (int o = 1; o < 32; o <<= 1) {
        int y = __shfl_up_sync(0xffffffffu, incl, o);
        if (lane >= o) incl += y;
    }
    if (t < 512 && lane == 31) wtmp[wid] = incl;
    __syncthreads();
    if (t < 16) {
        int w = wtmp[t], s = w;
#pragma unroll
        for (int o = 1; o < 16; o <<= 1) {
            int y = __shfl_up_sync(0x0000ffffu, s, o);
            if (t >= o) s += y;
        }
        wexcl[t] = s - w;
    }
    __syncthreads();
    if (t < 512) {
        int excl = incl - v + wexcl[wid];
        if (t < k) {
            int node = (g << 9) + t;
            d_coff[node] = e0 + excl;
            d_indeg[node] = v;
            float di = rsqrtf((float)v + 1.f);
            d_dinv[node] = di;
            dv[t] = di;
            scnt[t] = excl;
        }
    }
    __syncthreads();

    for (int i = t; i < EPG; i += 1024) {
        if (rk[i] >= 0) {
            int s2 = d_srcE[e0 + i], d2 = d_dstE[e0 + i];
            union { struct { int s; float c; } p; long long ll; } u;
            u.p.s = s2;
            u.p.c = dv[s2] * dv[d2];
            d_csr[e0 + scnt[d2] + rk[i]] = u.ll;
        }
    }
}

// ================= final MLP =================
__global__ __launch_bounds__(128) void k_final(const float* __restrict__ Wl1,
                                               const float* __restrict__ bl1,
                                               const float* __restrict__ Wl2,
                                               const float* __restrict__ bl2,
                                               float* __restrict__ out) {
    __shared__ float s[256];
    __shared__ float hid[128];
    int g = blockIdx.x, t = threadIdx.x;
    for (int i = t; i < 256; i += 128)
        s[i] = d_read[0 * NG * 256 + g * 256 + i] + d_read[1 * NG * 256 + g * 256 + i] +
               d_read[2 * NG * 256 + g * 256 + i];
    __syncthreads();
    float acc = bl1[t];
#pragma unroll 8
    for (int j = 0; j < 256; j++) acc += s[j] * Wl1[j * 128 + t];
    hid[t] = fmaxf(acc, 0.f);
    __syncthreads();
    if (t < 64) {
        int o = t >> 5, lane = t & 31;
        float p = 0.f;
#pragma unroll
        for (int j = lane; j < 128; j += 32) p += hid[j] * Wl2[j * 2 + o];
#pragma unroll
        for (int off = 16; off > 0; off >>= 1) p += __shfl_xor_sync(0xffffffffu, p, off);
        if (lane == 0) out[g * 2 + o] = p + bl2[o];
    }
}

// ================= orchestration =================
extern "C" void kernel_launch(void* const* d_in, const int* in_sizes, int n_in,
                              void* d_out, int out_size) {
    (void)in_sizes; (void)n_in; (void)out_size;
    const float* x = (const float*)d_in[0];
    const int* ei = (const int*)d_in[1];
    const float* Wp = (const float*)d_in[3];
    const float* bp = (const float*)d_in[4];
    const float* Wc[3] = {(const float*)d_in[5], (const float*)d_in[10], (const float*)d_in[15]};
    const float* bc[3] = {(const float*)d_in[6], (const float*)d_in[11], (const float*)d_in[16]};
    const float* gc[3] = {(const float*)d_in[7], (const float*)d_in[12], (const float*)d_in[17]};
    const float* be[3] = {(const float*)d_in[8], (const float*)d_in[13], (const float*)d_in[18]};
    const float* at[3] = {(const float*)d_in[9], (const float*)d_in[14], (const float*)d_in[19]};
    const float* Wl1 = (const float*)d_in[20];
    const float* bl1 = (const float*)d_in[21];
    const float* Wl2 = (const float*)d_in[22];
    const float* bl2 = (const float*)d_in[23];

    float *bufA, *bufB;
    cudaGetSymbolAddress((void**)&bufA, d_bufA);
    cudaGetSymbolAddress((void**)&bufB, d_bufB);

    cudaFuncSetAttribute(k_mm, cudaFuncAttributeMaxDynamicSharedMemorySize, MM_SMEM);
    cudaFuncSetAttribute(k_mm2, cudaFuncAttributeMaxDynamicSharedMemorySize, MM_SMEM);
    cudaFuncSetAttribute(k_conv, cudaFuncAttributeMaxDynamicSharedMemorySize, 65536);
    cudaFuncSetAttribute(k_topk, cudaFuncAttributeMaxDynamicSharedMemorySize, 40960);

    k_init<<<NG, 512>>>(ei, at[0], at[1], at[2]);
    k_mm2<<<N0TOT / 128, 256, MM_SMEM>>>(x, Wp, bp, Wc[0], bufB);
    k_conv<<<dim3(NG, 4), 512, NPER0 * 32 * sizeof(float)>>>(bufB, bufA, bc[0], NPER0, 0);
    k_topk<<<NG, 1024, EPG * sizeof(int)>>>(bufA, bufB, gc[0], be[0], at[0],
                                            NPER0, K1C, N0TOT, 0, 1);
    k_mm<<<N1TOT / 128, 256, MM_SMEM>>>(bufB, Wc[1], bufA);
    k_conv<<<dim3(NG, 4), 512, K1C * 32 * sizeof(float)>>>(bufA, bufB, bc[1], K1C, 1);
    k_topk<<<NG, 1024, EPG * sizeof(int)>>>(bufB, bufA, gc[1], be[1], at[1],
                                            K1C, K2C, N1TOT, 1, 1);
    k_mm<<<N2TOT / 128, 256, MM_SMEM>>>(bufA, Wc[2], bufB);
    k_conv<<<dim3(NG, 4), 512, K2C * 32 * sizeof(float)>>>(bufB, bufA, bc[2], K2C, 2);
    k_topk<<<NG, 1024, EPG * sizeof(int)>>>(bufA, bufB, gc[2], be[2], at[2],
                                            K2C, K3C, N2TOT, 2, 0);
    k_final<<<NG, 128>>>(Wl1, bl1, Wl2, bl2, (float*)d_out);
}